// round 3
// baseline (speedup 1.0000x reference)
#include <cuda_runtime.h>
#include <math.h>

// ConvolutionalCapsule EM routing, R3: 1024 threads/CTA (32 warps to hide LDS
// latency; smem already limits to 1 CTA/SM), 4-way split-I M-step, qq-outer
// E-step to fit the 64-reg/thread budget.
//
// One CTA per output position (1152 CTAs). Votes [144,16,16] fp32 in smem.
// Thread layout: t = h*256 + o*16 + p  (h in 0..3 = I-quarter for the M-step).

#define EPS 1e-9f
#define LOG2E 1.4426950408889634f
#define NPOS 1152
#define ICAP 144
#define NPAIR 2304
#define VOTES_F 36864

// smem layout (floats)
#define OFF_RR    36864          // [144][16] rr (aliased: im2col pose patch)
#define OFF_ACTS  39168          // [144]
#define OFF_PC    39312          // [3][3][256] M-step partials from quarters 1..3
#define OFF_A     41616          // [256] invd * log2e    (indexed o*16+p)
#define OFF_B     41872          // [256] mean * invd * log2e
#define OFF_C     42128          // [16]
#define SMEM_FLOATS 42144
#define SMEM_BYTES (SMEM_FLOATS * 4)

__global__ __launch_bounds__(1024, 1)
void caps_em_kernel(const float* __restrict__ pose_in,   // [8,14,14,256]
                    const float* __restrict__ act_in,    // [8,14,14,16]
                    const float* __restrict__ w,         // [144,16,4,4]
                    const float* __restrict__ beta_v,    // [16]
                    const float* __restrict__ beta_a,    // [16]
                    float* __restrict__ out)             // pose[1152,256] ++ act[1152,16]
{
    extern __shared__ float sm[];
    float* votes = sm;
    float* rr    = sm + OFF_RR;
    float* acts  = sm + OFF_ACTS;
    float* pc    = sm + OFF_PC;
    float* a_sm  = sm + OFF_A;
    float* b_sm  = sm + OFF_B;
    float* c_sm  = sm + OFF_C;

    const int n = blockIdx.x;
    const int x = n % 12;
    const int y = (n / 12) % 12;
    const int b = n / 144;
    const int t  = threadIdx.x;
    const int tt = t & 255;
    const int h  = t >> 8;
    const int o  = tt >> 4;
    const int p  = tt & 15;
    const int rot = ((t & 3) + ((t >> 2) & 1)) & 3;   // phase-conflict-free chunk rotation

    // ---- load im2col patch (aliased into rr) + acts ----
    for (int idx = t; idx < NPAIR; idx += 1024) {
        const int kp = idx >> 8, c = idx & 255;
        const int base = (b * 14 + (y + kp / 3)) * 14 + (x + kp % 3);
        rr[idx] = pose_in[base * 256 + c];
    }
    if (t < ICAP) {
        const int kp = t >> 4;
        const int base = (b * 14 + (y + kp / 3)) * 14 + (x + kp % 3);
        acts[t] = act_in[base * 16 + (t & 15)];
    }
    __syncthreads();

    // ---- votes[i,o] = pose4[i] @ w[i,o], rotated row order (conflict-free STS.128) ----
    for (int idx = t; idx < NPAIR; idx += 1024) {
        const int i = idx >> 4;
        const float4* pw = (const float4*)(w + (size_t)idx * 16);
        const float4 w0 = pw[0], w1 = pw[1], w2 = pw[2], w3 = pw[3];
        const float* pr = rr + i * 16;
        float4* vout = (float4*)(votes + idx * 16);
        #pragma unroll
        for (int rq = 0; rq < 4; ++rq) {
            const int r = (rq + rot) & 3;
            const float a0 = pr[r * 4 + 0], a1 = pr[r * 4 + 1];
            const float a2 = pr[r * 4 + 2], a3 = pr[r * 4 + 3];
            float4 res;
            res.x = a0 * w0.x + a1 * w1.x + a2 * w2.x + a3 * w3.x;
            res.y = a0 * w0.y + a1 * w1.y + a2 * w2.y + a3 * w3.y;
            res.z = a0 * w0.z + a1 * w1.z + a2 * w2.z + a3 * w3.z;
            res.w = a0 * w0.w + a1 * w1.w + a2 * w2.w + a3 * w3.w;
            vout[r] = res;
        }
    }
    __syncthreads();

    float bv = 0.f, ba = 0.f;
    if (t < 256) { bv = beta_v[o]; ba = beta_a[o]; }

    for (int it = 0; it < 3; ++it) {
        // ---- M-step: this quarter's 36 input capsules ----
        float S0 = 0.f, S1 = 0.f, S2 = 0.f;
        const int i0 = h * 36;
        if (it == 0) {
            #pragma unroll 4
            for (int i = i0; i < i0 + 36; ++i) {
                const float rp = acts[i] * 0.0625f;
                const float v  = votes[i * 256 + tt];
                const float t1 = rp * v;
                S0 += rp; S1 += t1; S2 += t1 * v;
            }
        } else {
            #pragma unroll 4
            for (int i = i0; i < i0 + 36; ++i) {
                const float rp = rr[i * 16 + o];          // already *acts (folded in softmax)
                const float v  = votes[i * 256 + tt];
                const float t1 = rp * v;
                S0 += rp; S1 += t1; S2 += t1 * v;
            }
        }
        if (h) {
            float* q = pc + (h - 1) * 768;
            q[tt] = S0; q[256 + tt] = S1; q[512 + tt] = S2;
        }
        __syncthreads();

        if (t < 256) {
            #pragma unroll
            for (int j = 0; j < 3; ++j) {
                S0 += pc[j * 768 + t];
                S1 += pc[j * 768 + 256 + t];
                S2 += pc[j * 768 + 512 + t];
            }
            const float mean = S1 / (S0 + EPS);
            float varsum = S2 - 2.f * mean * S1 + mean * mean * S0;
            varsum = fmaxf(varsum, 0.f);
            const float stdv = sqrtf(varsum / (S0 + EPS));
            const float lg   = logf(stdv + EPS);
            const float invd = 1.f / (2.f * stdv * stdv + EPS);
            const float av   = invd * LOG2E;
            const float bco  = mean * av;

            // butterfly over 16 pose dims: L = sum lg ; MB = sum mean*bco
            float L = lg, MB = mean * bco;
            #pragma unroll
            for (int d = 8; d; d >>= 1) {
                L  += __shfl_xor_sync(0xffffffffu, L,  d);
                MB += __shfl_xor_sync(0xffffffffu, MB, d);
            }

            const float costsum = (16.f * bv + L) * S0;
            const float itemp = 1.f + (float)it;
            const float oact = 1.f / (1.f + expf(-(itemp * (ba - costsum))));

            if (it == 2) {
                out[n * 256 + t] = mean;
                if (p == 0) out[NPOS * 256 + n * 16 + o] = oact;
            } else {
                a_sm[t] = av;
                b_sm[t] = bco;
                if (p == 0) c_sm[o] = (logf(oact + EPS) - L) * LOG2E - MB;
            }
        }
        __syncthreads();
        if (it == 2) break;

        // ---- E-step: zz2[idx] = C[oo] - sum_p v*(v*a - 2b)  (qq-outer, regs <= 64) ----
        {
            const int oo = t & 15;
            float4 s0 = make_float4(0.f, 0.f, 0.f, 0.f);
            float4 s1 = make_float4(0.f, 0.f, 0.f, 0.f);
            #pragma unroll
            for (int qq = 0; qq < 4; ++qq) {
                const int q = (qq + rot) & 3;
                const float4 A = ((const float4*)a_sm)[(oo << 2) | q];
                float4 Bb = ((const float4*)b_sm)[(oo << 2) | q];
                Bb.x *= -2.f; Bb.y *= -2.f; Bb.z *= -2.f; Bb.w *= -2.f;

                float4 v = ((const float4*)votes)[(t << 2) | q];
                s0.x = fmaf(v.x, fmaf(v.x, A.x, Bb.x), s0.x);
                s0.y = fmaf(v.y, fmaf(v.y, A.y, Bb.y), s0.y);
                s0.z = fmaf(v.z, fmaf(v.z, A.z, Bb.z), s0.z);
                s0.w = fmaf(v.w, fmaf(v.w, A.w, Bb.w), s0.w);

                v = ((const float4*)votes)[((t + 1024) << 2) | q];
                s1.x = fmaf(v.x, fmaf(v.x, A.x, Bb.x), s1.x);
                s1.y = fmaf(v.y, fmaf(v.y, A.y, Bb.y), s1.y);
                s1.z = fmaf(v.z, fmaf(v.z, A.z, Bb.z), s1.z);
                s1.w = fmaf(v.w, fmaf(v.w, A.w, Bb.w), s1.w);
            }
            const float C = c_sm[oo];
            rr[t]        = C - ((s0.x + s0.y) + (s0.z + s0.w));
            rr[t + 1024] = C - ((s1.x + s1.y) + (s1.z + s1.w));

            if (t < 256) {                       // tail: pairs 2048..2303
                float4 s2 = make_float4(0.f, 0.f, 0.f, 0.f);
                #pragma unroll
                for (int qq = 0; qq < 4; ++qq) {
                    const int q = (qq + rot) & 3;
                    const float4 A = ((const float4*)a_sm)[(oo << 2) | q];
                    float4 Bb = ((const float4*)b_sm)[(oo << 2) | q];
                    Bb.x *= -2.f; Bb.y *= -2.f; Bb.z *= -2.f; Bb.w *= -2.f;
                    const float4 v = ((const float4*)votes)[((t + 2048) << 2) | q];
                    s2.x = fmaf(v.x, fmaf(v.x, A.x, Bb.x), s2.x);
                    s2.y = fmaf(v.y, fmaf(v.y, A.y, Bb.y), s2.y);
                    s2.z = fmaf(v.z, fmaf(v.z, A.z, Bb.z), s2.z);
                    s2.w = fmaf(v.w, fmaf(v.w, A.w, Bb.w), s2.w);
                }
                rr[t + 2048] = C - ((s2.x + s2.y) + (s2.z + s2.w));
            }
        }
        __syncthreads();

        // ---- softmax over o (base 2) per input capsule, scaled by acts[i] ----
        if (t < ICAP) {
            float4 z[4];
            #pragma unroll
            for (int qq = 0; qq < 4; ++qq) {
                const int q = (qq + rot) & 3;
                z[qq] = ((const float4*)rr)[(t << 2) | q];
            }
            float mx = -3.4e38f;
            #pragma unroll
            for (int qq = 0; qq < 4; ++qq)
                mx = fmaxf(mx, fmaxf(fmaxf(z[qq].x, z[qq].y), fmaxf(z[qq].z, z[qq].w)));
            float ss = 0.f;
            #pragma unroll
            for (int qq = 0; qq < 4; ++qq) {
                z[qq].x = exp2f(z[qq].x - mx); ss += z[qq].x;
                z[qq].y = exp2f(z[qq].y - mx); ss += z[qq].y;
                z[qq].z = exp2f(z[qq].z - mx); ss += z[qq].z;
                z[qq].w = exp2f(z[qq].w - mx); ss += z[qq].w;
            }
            const float scale = acts[t] / ss;    // fold acts into rr
            #pragma unroll
            for (int qq = 0; qq < 4; ++qq) {
                const int q = (qq + rot) & 3;
                float4 zz = z[qq];
                zz.x *= scale; zz.y *= scale; zz.z *= scale; zz.w *= scale;
                ((float4*)rr)[(t << 2) | q] = zz;
            }
        }
        __syncthreads();
    }
}

extern "C" void kernel_launch(void* const* d_in, const int* in_sizes, int n_in,
                              void* d_out, int out_size) {
    const float* pose_in = (const float*)d_in[0];
    const float* act_in  = (const float*)d_in[1];
    const float* w       = (const float*)d_in[2];
    const float* beta_v  = (const float*)d_in[3];
    const float* beta_a  = (const float*)d_in[4];
    float* out = (float*)d_out;

    cudaFuncSetAttribute(caps_em_kernel,
                         cudaFuncAttributeMaxDynamicSharedMemorySize, SMEM_BYTES);
    caps_em_kernel<<<NPOS, 1024, SMEM_BYTES>>>(pose_in, act_in, w, beta_v, beta_a, out);
}

// round 6
// speedup vs baseline: 1.0003x; 1.0003x over previous
#include <cuda_runtime.h>
#include <math.h>

// ConvolutionalCapsule EM routing, R4: 512 threads/CTA.
//  - M-step: 8-way I-split, thread = (h, o, p-quad), votes read as LDS.128.
//  - E-step fused with softmax: 16-lane half-warp butterflies, no smem
//    round-trip, no separate softmax phase, one fewer barrier.
//  - rr keeps [i][o] layout; acts folded into rr at softmax time.
//
// One CTA per output position (1152 CTAs). Votes [144,16,16] fp32 in smem.

#define EPS 1e-9f
#define LOG2E 1.4426950408889634f
#define NPOS 1152
#define ICAP 144
#define NPAIR 2304

// smem layout (floats)
#define OFF_RR    36864          // [144][16] rr (aliased: im2col pose patch)
#define OFF_ACTS  39168          // [144]
#define OFF_PC    39312          // [8][64][12] M-step partials (S1[4],S2[4],S0,pad)
#define OFF_A     45456          // [256] invd * log2e   (indexed o*16+p)
#define OFF_B     45712          // [256] mean * invd * log2e
#define OFF_C     45968          // [16]
#define SMEM_FLOATS 45984
#define SMEM_BYTES (SMEM_FLOATS * 4)

__global__ __launch_bounds__(512, 1)
void caps_em_kernel(const float* __restrict__ pose_in,   // [8,14,14,256]
                    const float* __restrict__ act_in,    // [8,14,14,16]
                    const float* __restrict__ w,         // [144,16,4,4]
                    const float* __restrict__ beta_v,    // [16]
                    const float* __restrict__ beta_a,    // [16]
                    float* __restrict__ out)             // pose[1152,256] ++ act[1152,16]
{
    extern __shared__ float sm[];
    float* votes = sm;
    float* rr    = sm + OFF_RR;
    float* acts  = sm + OFF_ACTS;
    float* pc    = sm + OFF_PC;
    float* a_sm  = sm + OFF_A;
    float* b_sm  = sm + OFF_B;
    float* c_sm  = sm + OFF_C;

    const int n = blockIdx.x;
    const int x = n % 12;
    const int y = (n / 12) % 12;
    const int b = n / 144;
    const int t  = threadIdx.x;
    const int rot = ((t & 3) + ((t >> 2) & 1)) & 3;   // phase-conflict-free chunk rotation

    // M-step mapping: 8-way I-split
    const int h  = t >> 6;          // 0..7
    const int om = (t >> 2) & 15;   // output capsule
    const int pq = t & 3;           // pose-quad
    // combine mapping (t < 256)
    const int o = (t >> 4) & 15;
    const int p = t & 15;

    // ---- load im2col patch (aliased into rr) + acts ----
    for (int idx = t; idx < NPAIR; idx += 512) {
        const int kp = idx >> 8, c = idx & 255;
        const int base = (b * 14 + (y + kp / 3)) * 14 + (x + kp % 3);
        rr[idx] = pose_in[base * 256 + c];
    }
    if (t < ICAP) {
        const int kp = t >> 4;
        const int base = (b * 14 + (y + kp / 3)) * 14 + (x + kp % 3);
        acts[t] = act_in[base * 16 + (t & 15)];
    }
    __syncthreads();

    // ---- votes[i,o] = pose4[i] @ w[i,o], rotated row order (conflict-free STS.128) ----
    for (int idx = t; idx < NPAIR; idx += 512) {
        const int i = idx >> 4;
        const float4* pw = (const float4*)(w + (size_t)idx * 16);
        const float4 w0 = pw[0], w1 = pw[1], w2 = pw[2], w3 = pw[3];
        const float* pr = rr + i * 16;
        float4* vout = (float4*)(votes + idx * 16);
        #pragma unroll
        for (int rq = 0; rq < 4; ++rq) {
            const int r = (rq + rot) & 3;
            const float a0 = pr[r * 4 + 0], a1 = pr[r * 4 + 1];
            const float a2 = pr[r * 4 + 2], a3 = pr[r * 4 + 3];
            float4 res;
            res.x = a0 * w0.x + a1 * w1.x + a2 * w2.x + a3 * w3.x;
            res.y = a0 * w0.y + a1 * w1.y + a2 * w2.y + a3 * w3.y;
            res.z = a0 * w0.z + a1 * w1.z + a2 * w2.z + a3 * w3.z;
            res.w = a0 * w0.w + a1 * w1.w + a2 * w2.w + a3 * w3.w;
            vout[r] = res;
        }
    }
    __syncthreads();

    float bv = 0.f, ba = 0.f;
    if (t < 256) { bv = beta_v[o]; ba = beta_a[o]; }

    const int i0 = h * 18;
    float* mypc = pc + (size_t)(h * 64 + om * 4 + pq) * 12;
    const float4* vt4 = (const float4*)votes;

    for (int it = 0; it < 3; ++it) {
        // ---- M-step partials: 18 input capsules, votes via LDS.128 ----
        float  S0 = 0.f;
        float4 S1 = make_float4(0.f, 0.f, 0.f, 0.f);
        float4 S2 = make_float4(0.f, 0.f, 0.f, 0.f);
        if (it == 0) {
            #pragma unroll 6
            for (int i = i0; i < i0 + 18; ++i) {
                const float rp = acts[i] * 0.0625f;
                const float4 v = vt4[i * 64 + om * 4 + pq];
                S0 += rp;
                const float t0 = rp * v.x, t1 = rp * v.y, t2 = rp * v.z, t3 = rp * v.w;
                S1.x += t0; S1.y += t1; S1.z += t2; S1.w += t3;
                S2.x = fmaf(t0, v.x, S2.x); S2.y = fmaf(t1, v.y, S2.y);
                S2.z = fmaf(t2, v.z, S2.z); S2.w = fmaf(t3, v.w, S2.w);
            }
        } else {
            #pragma unroll 6
            for (int i = i0; i < i0 + 18; ++i) {
                const float rp = rr[i * 16 + om];          // already * acts (folded)
                const float4 v = vt4[i * 64 + om * 4 + pq];
                S0 += rp;
                const float t0 = rp * v.x, t1 = rp * v.y, t2 = rp * v.z, t3 = rp * v.w;
                S1.x += t0; S1.y += t1; S1.z += t2; S1.w += t3;
                S2.x = fmaf(t0, v.x, S2.x); S2.y = fmaf(t1, v.y, S2.y);
                S2.z = fmaf(t2, v.z, S2.z); S2.w = fmaf(t3, v.w, S2.w);
            }
        }
        ((float4*)mypc)[0] = S1;
        ((float4*)mypc)[1] = S2;
        mypc[8] = S0;
        __syncthreads();

        // ---- combine + statistics (threads 0..255 = (o,p)) ----
        if (t < 256) {
            const int g  = o * 4 + (p >> 2);
            const int pe = p & 3;
            float s0 = 0.f, s1 = 0.f, s2 = 0.f;
            #pragma unroll
            for (int hh = 0; hh < 8; ++hh) {
                const float* q = pc + (size_t)(hh * 64 + g) * 12;
                s1 += q[pe]; s2 += q[4 + pe]; s0 += q[8];
            }
            const float mean = s1 / (s0 + EPS);
            float varsum = s2 - 2.f * mean * s1 + mean * mean * s0;
            varsum = fmaxf(varsum, 0.f);
            const float stdv = sqrtf(varsum / (s0 + EPS));
            const float lg   = logf(stdv + EPS);
            const float invd = 1.f / (2.f * stdv * stdv + EPS);
            const float av   = invd * LOG2E;
            const float bco  = mean * av;

            float L = lg, MB = mean * bco;
            #pragma unroll
            for (int d = 8; d; d >>= 1) {
                L  += __shfl_xor_sync(0xffffffffu, L,  d);
                MB += __shfl_xor_sync(0xffffffffu, MB, d);
            }

            const float costsum = (16.f * bv + L) * s0;
            const float itemp = 1.f + (float)it;
            const float oact = 1.f / (1.f + expf(-(itemp * (ba - costsum))));

            if (it == 2) {
                out[n * 256 + t] = mean;
                if (p == 0) out[NPOS * 256 + n * 16 + o] = oact;
            } else {
                a_sm[t] = av;
                b_sm[t] = bco;
                if (p == 0) c_sm[o] = (logf(oact + EPS) - L) * LOG2E - MB;
            }
        }
        __syncthreads();
        if (it == 2) break;

        // ---- fused E-step + softmax (16-lane groups own zz rows) ----
        {
            const int oo = t & 15;
            float4 A4[4], B4[4];
            #pragma unroll
            for (int qq = 0; qq < 4; ++qq) {
                const int q = (qq + rot) & 3;
                A4[qq] = ((const float4*)a_sm)[(oo << 2) | q];
                float4 bb = ((const float4*)b_sm)[(oo << 2) | q];
                bb.x *= -2.f; bb.y *= -2.f; bb.z *= -2.f; bb.w *= -2.f;
                B4[qq] = bb;
            }
            const float C = c_sm[oo];
            const int ib = t >> 4;

            #pragma unroll
            for (int k = 0; k < 4; ++k) {
                const int idx = t + 512 * k;
                const int i   = ib + 32 * k;
                float4 s = make_float4(0.f, 0.f, 0.f, 0.f);
                #pragma unroll
                for (int qq = 0; qq < 4; ++qq) {
                    const int q = (qq + rot) & 3;
                    const float4 v = vt4[(idx << 2) | q];
                    s.x = fmaf(v.x, fmaf(v.x, A4[qq].x, B4[qq].x), s.x);
                    s.y = fmaf(v.y, fmaf(v.y, A4[qq].y, B4[qq].y), s.y);
                    s.z = fmaf(v.z, fmaf(v.z, A4[qq].z, B4[qq].z), s.z);
                    s.w = fmaf(v.w, fmaf(v.w, A4[qq].w, B4[qq].w), s.w);
                }
                const float zz = C - ((s.x + s.y) + (s.z + s.w));
                float mx = zz;
                #pragma unroll
                for (int d = 8; d; d >>= 1)
                    mx = fmaxf(mx, __shfl_xor_sync(0xffffffffu, mx, d));
                const float e = exp2f(zz - mx);
                float ssum = e;
                #pragma unroll
                for (int d = 8; d; d >>= 1)
                    ssum += __shfl_xor_sync(0xffffffffu, ssum, d);
                rr[idx] = e * acts[i] / ssum;
            }
            if (t < 256) {   // tail rows 128..143 (warps 0..7, uniform)
                const int idx = t + 2048;
                const int i   = ib + 128;
                float4 s = make_float4(0.f, 0.f, 0.f, 0.f);
                #pragma unroll
                for (int qq = 0; qq < 4; ++qq) {
                    const int q = (qq + rot) & 3;
                    const float4 v = vt4[(idx << 2) | q];
                    s.x = fmaf(v.x, fmaf(v.x, A4[qq].x, B4[qq].x), s.x);
                    s.y = fmaf(v.y, fmaf(v.y, A4[qq].y, B4[qq].y), s.y);
                    s.z = fmaf(v.z, fmaf(v.z, A4[qq].z, B4[qq].z), s.z);
                    s.w = fmaf(v.w, fmaf(v.w, A4[qq].w, B4[qq].w), s.w);
                }
                const float zz = C - ((s.x + s.y) + (s.z + s.w));
                float mx = zz;
                #pragma unroll
                for (int d = 8; d; d >>= 1)
                    mx = fmaxf(mx, __shfl_xor_sync(0xffffffffu, mx, d));
                const float e = exp2f(zz - mx);
                float ssum = e;
                #pragma unroll
                for (int d = 8; d; d >>= 1)
                    ssum += __shfl_xor_sync(0xffffffffu, ssum, d);
                rr[idx] = e * acts[i] / ssum;
            }
        }
        __syncthreads();
    }
}

extern "C" void kernel_launch(void* const* d_in, const int* in_sizes, int n_in,
                              void* d_out, int out_size) {
    const float* pose_in = (const float*)d_in[0];
    const float* act_in  = (const float*)d_in[1];
    const float* w       = (const float*)d_in[2];
    const float* beta_v  = (const float*)d_in[3];
    const float* beta_a  = (const float*)d_in[4];
    float* out = (float*)d_out;

    cudaFuncSetAttribute(caps_em_kernel,
                         cudaFuncAttributeMaxDynamicSharedMemorySize, SMEM_BYTES);
    caps_em_kernel<<<NPOS, 512, SMEM_BYTES>>>(pose_in, act_in, w, beta_v, beta_a, out);
}